// round 10
// baseline (speedup 1.0000x reference)
#include <cuda_runtime.h>
#include <cuda_fp16.h>
#include <cstdint>

// ----------------------------------------------------------------------------
// GNNLayer: out = relu(x @ W^T + b); out[col[e],0] += x[e,0]
// fp16 mma.sync GEMM, CTA tile 128x256, warp tile 64x64 (smem-traffic halved).
// ----------------------------------------------------------------------------

#define IN_DIM  512
#define OUT_DIM 512
#define MAXROWS 100096          // 782*128
#define BM      128
#define BN      256
#define BK      64
#define NCHUNK  (IN_DIM / BK)   // 8
#define THREADS 256

// smem rows padded to 144B (64 fp16 = 128B + 16B pad) -> ldmatrix conflict-free
#define ROWB    144
#define A_OFF   0
#define B_OFF   (BM * ROWB)                  // 18432
#define STAGE   ((BM + BN) * ROWB)           // 55296
#define NSTAGE  3
#define SM_TOTAL (NSTAGE * STAGE)            // 165888

__device__ __half g_Wh[OUT_DIM * IN_DIM];
__device__ __half g_xh[MAXROWS * IN_DIM];

__device__ __forceinline__ uint32_t smem_u32(const void* p) {
    uint32_t a;
    asm("{ .reg .u64 t; cvta.to.shared.u64 t, %1; cvt.u32.u64 %0, t; }" : "=r"(a) : "l"(p));
    return a;
}
__device__ __forceinline__ void ldx4(uint32_t r[4], uint32_t addr) {
    asm volatile("ldmatrix.sync.aligned.m8n8.x4.shared.b16 {%0,%1,%2,%3}, [%4];"
                 : "=r"(r[0]), "=r"(r[1]), "=r"(r[2]), "=r"(r[3]) : "r"(addr));
}
__device__ __forceinline__ void mma16816(float c[4], const uint32_t a[4], const uint32_t b[2]) {
    asm volatile("mma.sync.aligned.m16n8k16.row.col.f32.f16.f16.f32 "
                 "{%0,%1,%2,%3}, {%4,%5,%6,%7}, {%8,%9}, {%0,%1,%2,%3};"
                 : "+f"(c[0]), "+f"(c[1]), "+f"(c[2]), "+f"(c[3])
                 : "r"(a[0]), "r"(a[1]), "r"(a[2]), "r"(a[3]), "r"(b[0]), "r"(b[1]));
}
__device__ __forceinline__ void cp16(uint32_t dst, const void* src) {
    asm volatile("cp.async.cg.shared.global [%0], [%1], 16;"
                 :: "r"(dst), "l"(__cvta_generic_to_global(src)));
}

// ---------------- prep: convert x AND W to fp16 (one kernel) ------------------
#define WN4 (OUT_DIM * IN_DIM / 4)           // 65536 float4 of W
__global__ __launch_bounds__(256)
void conv_xw_kernel(const float* __restrict__ x, const float* __restrict__ W, int n4) {
    int i = blockIdx.x * blockDim.x + threadIdx.x;
    if (i < n4) {
        float4 v = reinterpret_cast<const float4*>(x)[i];
        __half2 p0 = __floats2half2_rn(v.x, v.y);
        __half2 p1 = __floats2half2_rn(v.z, v.w);
        uint2 o;
        o.x = *reinterpret_cast<uint32_t*>(&p0);
        o.y = *reinterpret_cast<uint32_t*>(&p1);
        reinterpret_cast<uint2*>(g_xh)[i] = o;
    }
    if (i < WN4) {
        float4 v = reinterpret_cast<const float4*>(W)[i];
        __half2 p0 = __floats2half2_rn(v.x, v.y);
        __half2 p1 = __floats2half2_rn(v.z, v.w);
        uint2 o;
        o.x = *reinterpret_cast<uint32_t*>(&p0);
        o.y = *reinterpret_cast<uint32_t*>(&p1);
        reinterpret_cast<uint2*>(g_Wh)[i] = o;
    }
}

// ---------------- main GEMM kernel (mma.sync fp16, 64x64 warp tile) -----------
__global__ __launch_bounds__(THREADS, 1)
void gemm_mma_kernel(const float* __restrict__ bias,
                     float* __restrict__ C, int M) {
    extern __shared__ char smem[];
    const uint32_t sb = smem_u32(smem);
    const int tid    = threadIdx.x;
    const int lane   = tid & 31;
    const int wid    = tid >> 5;
    const int warp_m = wid >> 2;          // 0..1 (64 rows each)
    const int warp_n = wid & 3;           // 0..3 (64 cols each)
    const int row0   = blockIdx.y * BM;
    const int n0     = blockIdx.x * BN;

    // ldmatrix lane-address components
    const uint32_t arow  = (uint32_t)(warp_m * 64 + (lane & 15));
    const uint32_t acolq = (uint32_t)((lane >> 4) << 3) * 2;        // 0 or 16B
    // B ldx4 pairing (ni=2p, 2p+1): q = lane>>3
    const uint32_t bq    = (uint32_t)(lane >> 3);                    // 0..3
    const uint32_t brsel = (uint32_t)(lane & 7);

    float acc[4][8][4];
    #pragma unroll
    for (int mi = 0; mi < 4; mi++)
        #pragma unroll
        for (int ni = 0; ni < 8; ni++)
            #pragma unroll
            for (int j = 0; j < 4; j++) acc[mi][ni][j] = 0.f;

    auto issue = [&](int kt, int st) {
        const int k0 = kt * BK;
        const uint32_t sbase = sb + st * STAGE;
        // A: 128 rows x 8 units = 1024 cp16 (4/thread)
        #pragma unroll
        for (int i = 0; i < 4; i++) {
            int idx = i * THREADS + tid;
            int r = idx >> 3, u = idx & 7;
            cp16(sbase + A_OFF + r * ROWB + u * 16,
                 g_xh + (size_t)(row0 + r) * IN_DIM + k0 + u * 8);
        }
        // B: 256 rows x 8 units = 2048 cp16 (8/thread)
        #pragma unroll
        for (int i = 0; i < 8; i++) {
            int idx = i * THREADS + tid;
            int r = idx >> 3, u = idx & 7;
            cp16(sbase + B_OFF + r * ROWB + u * 16,
                 g_Wh + (size_t)(n0 + r) * IN_DIM + k0 + u * 8);
        }
        asm volatile("cp.async.commit_group;" ::: "memory");
    };

    // ---- prologue: 2 chunks in flight ---------------------------------------
    issue(0, 0);
    issue(1, 1);

    // ---- main loop ----------------------------------------------------------
    for (int kt = 0; kt < NCHUNK; kt++) {
        const int st = kt % NSTAGE;
        asm volatile("cp.async.wait_group 1;" ::: "memory");   // chunk kt ready
        __syncthreads();

        // prefetch chunk kt+2 as early as possible (stage (kt+2)%3 was
        // consumed at chunk kt-1, which all warps finished before the barrier)
        if (kt + 2 < NCHUNK) issue(kt + 2, (kt + 2) % NSTAGE);
        else asm volatile("cp.async.commit_group;" ::: "memory"); // keep count

        const uint32_t sbase = sb + st * STAGE;
        #pragma unroll
        for (int s = 0; s < 4; s++) {
            const uint32_t kb = (uint32_t)(s * 16) * 2;         // 32B per k16

            // A fragments: 4 x ldx4
            uint32_t af[4][4];
            #pragma unroll
            for (int mi = 0; mi < 4; mi++)
                ldx4(af[mi], sbase + A_OFF + (arow + mi * 16) * ROWB + kb + acolq);

            // B fragments: 4 x ldx4, each covering ni pair (2p, 2p+1)
            uint32_t bf[8][2];
            #pragma unroll
            for (int p = 0; p < 4; p++) {
                uint32_t brow = (uint32_t)(warp_n * 64 + (2 * p + (bq >> 1)) * 8 + brsel);
                uint32_t baddr = sbase + B_OFF + brow * ROWB + kb + (bq & 1) * 16;
                uint32_t r[4];
                ldx4(r, baddr);
                bf[2*p][0]   = r[0]; bf[2*p][1]   = r[1];
                bf[2*p+1][0] = r[2]; bf[2*p+1][1] = r[3];
            }

            #pragma unroll
            for (int mi = 0; mi < 4; mi++)
                #pragma unroll
                for (int ni = 0; ni < 8; ni++)
                    mma16816(acc[mi][ni], af[mi], bf[ni]);
        }
    }

    // ---- epilogue: bias + relu + float2 stores ------------------------------
    #pragma unroll
    for (int mi = 0; mi < 4; mi++) {
        int r = row0 + warp_m * 64 + mi * 16 + (lane >> 2);
        #pragma unroll
        for (int ni = 0; ni < 8; ni++) {
            int col = n0 + warp_n * 64 + ni * 8 + (lane & 3) * 2;
            float2 bv = *reinterpret_cast<const float2*>(bias + col);
            if (r < M) {
                float2 o;
                o.x = fmaxf(acc[mi][ni][0] + bv.x, 0.f);
                o.y = fmaxf(acc[mi][ni][1] + bv.y, 0.f);
                *reinterpret_cast<float2*>(C + (size_t)r * OUT_DIM + col) = o;
            }
            if (r + 8 < M) {
                float2 o;
                o.x = fmaxf(acc[mi][ni][2] + bv.x, 0.f);
                o.y = fmaxf(acc[mi][ni][3] + bv.y, 0.f);
                *reinterpret_cast<float2*>(C + (size_t)(r + 8) * OUT_DIM + col) = o;
            }
        }
    }
}

// ---------------- scatter-add on column 0 -------------------------------------
__global__ void scatter_add_col0_kernel(const float* __restrict__ x,
                                        const int* __restrict__ edge_index,
                                        float* __restrict__ out,
                                        int E) {
    int e = blockIdx.x * blockDim.x + threadIdx.x;
    if (e < E) {
        int c = edge_index[E + e];            // row 1 of [2,E] int32
        atomicAdd(&out[(size_t)c * OUT_DIM], x[(size_t)e * IN_DIM]);
    }
}

// ---------------- launch ------------------------------------------------------
extern "C" void kernel_launch(void* const* d_in, const int* in_sizes, int n_in,
                              void* d_out, int out_size) {
    const float* x   = (const float*)d_in[0];
    const int*   ei  = (const int*)d_in[1];
    const float* W   = (const float*)d_in[2];
    const float* b   = (const float*)d_in[3];
    float*       out = (float*)d_out;

    const int M = in_sizes[0] / IN_DIM;
    const int E = in_sizes[1] / 2;

    cudaFuncSetAttribute(gemm_mma_kernel, cudaFuncAttributeMaxDynamicSharedMemorySize, SM_TOTAL);

    const int n4 = M * IN_DIM / 4;
    conv_xw_kernel<<<(n4 + 255) / 256, 256>>>(x, W, n4);

    dim3 grid(OUT_DIM / BN, (M + BM - 1) / BM);   // 2 x 782
    gemm_mma_kernel<<<grid, THREADS, SM_TOTAL>>>(b, out, M);

    scatter_add_col0_kernel<<<(E + 255) / 256, 256>>>(x, ei, out, E);
}

// round 11
// speedup vs baseline: 1.0923x; 1.0923x over previous
#include <cuda_runtime.h>
#include <cuda_fp16.h>
#include <cstdint>

// ----------------------------------------------------------------------------
// GNNLayer: out = relu(x @ W^T + b); out[col[e],0] += x[e,0]
// fp16 mma.sync GEMM. CTA 128x128 with 4 warps (2x2) of 64x64 tiles;
// 2 CTAs/SM (221KB smem) -> tensor-bound with cross-CTA latency cover.
// ----------------------------------------------------------------------------

#define IN_DIM  512
#define OUT_DIM 512
#define MAXROWS 100096          // 782*128
#define BM      128
#define BN      128
#define BK      64
#define NCHUNK  (IN_DIM / BK)   // 8
#define THREADS 128

// smem rows padded to 144B (64 fp16 = 128B + 16B pad) -> ldmatrix conflict-free
#define ROWB    144
#define A_OFF   0
#define B_OFF   (BM * ROWB)                  // 18432
#define STAGE   ((BM + BN) * ROWB)           // 36864
#define NSTAGE  3
#define SM_TOTAL (NSTAGE * STAGE)            // 110592 (x2 CTA = 221184 <= 228KB)

__device__ __half g_Wh[OUT_DIM * IN_DIM];
__device__ __half g_xh[MAXROWS * IN_DIM];

__device__ __forceinline__ uint32_t smem_u32(const void* p) {
    uint32_t a;
    asm("{ .reg .u64 t; cvta.to.shared.u64 t, %1; cvt.u32.u64 %0, t; }" : "=r"(a) : "l"(p));
    return a;
}
__device__ __forceinline__ void ldx4(uint32_t r[4], uint32_t addr) {
    asm volatile("ldmatrix.sync.aligned.m8n8.x4.shared.b16 {%0,%1,%2,%3}, [%4];"
                 : "=r"(r[0]), "=r"(r[1]), "=r"(r[2]), "=r"(r[3]) : "r"(addr));
}
__device__ __forceinline__ void ldx2(uint32_t r[2], uint32_t addr) {
    asm volatile("ldmatrix.sync.aligned.m8n8.x2.shared.b16 {%0,%1}, [%2];"
                 : "=r"(r[0]), "=r"(r[1]) : "r"(addr));
}
__device__ __forceinline__ void mma16816(float c[4], const uint32_t a[4], const uint32_t b[2]) {
    asm volatile("mma.sync.aligned.m16n8k16.row.col.f32.f16.f16.f32 "
                 "{%0,%1,%2,%3}, {%4,%5,%6,%7}, {%8,%9}, {%0,%1,%2,%3};"
                 : "+f"(c[0]), "+f"(c[1]), "+f"(c[2]), "+f"(c[3])
                 : "r"(a[0]), "r"(a[1]), "r"(a[2]), "r"(a[3]), "r"(b[0]), "r"(b[1]));
}
__device__ __forceinline__ void cp16(uint32_t dst, const void* src) {
    asm volatile("cp.async.cg.shared.global [%0], [%1], 16;"
                 :: "r"(dst), "l"(__cvta_generic_to_global(src)));
}

// ---------------- prep: convert x AND W to fp16 (one kernel, ~48us) -----------
#define WN4 (OUT_DIM * IN_DIM / 4)
__global__ __launch_bounds__(256)
void conv_xw_kernel(const float* __restrict__ x, const float* __restrict__ W, int n4) {
    int i = blockIdx.x * blockDim.x + threadIdx.x;
    if (i < n4) {
        float4 v = reinterpret_cast<const float4*>(x)[i];
        __half2 p0 = __floats2half2_rn(v.x, v.y);
        __half2 p1 = __floats2half2_rn(v.z, v.w);
        uint2 o;
        o.x = *reinterpret_cast<uint32_t*>(&p0);
        o.y = *reinterpret_cast<uint32_t*>(&p1);
        reinterpret_cast<uint2*>(g_xh)[i] = o;
    }
    if (i < WN4) {
        float4 v = reinterpret_cast<const float4*>(W)[i];
        __half2 p0 = __floats2half2_rn(v.x, v.y);
        __half2 p1 = __floats2half2_rn(v.z, v.w);
        uint2 o;
        o.x = *reinterpret_cast<uint32_t*>(&p0);
        o.y = *reinterpret_cast<uint32_t*>(&p1);
        reinterpret_cast<uint2*>(g_Wh)[i] = o;
    }
}

// ---------------- main GEMM kernel --------------------------------------------
__global__ __launch_bounds__(THREADS, 2)
void gemm_mma_kernel(const float* __restrict__ bias,
                     float* __restrict__ C, int M) {
    extern __shared__ char smem[];
    const uint32_t sb = smem_u32(smem);
    const int tid    = threadIdx.x;
    const int lane   = tid & 31;
    const int wid    = tid >> 5;          // 0..3
    const int warp_m = wid >> 1;          // 0..1 (64 rows)
    const int warp_n = wid & 1;           // 0..1 (64 cols)
    const int row0   = blockIdx.y * BM;
    const int n0     = blockIdx.x * BN;

    // ldmatrix lane-address components (R7-proven patterns)
    const uint32_t arow  = (uint32_t)(warp_m * 64 + (lane & 15));
    const uint32_t acolq = (uint32_t)((lane >> 4) << 3) * 2;        // 0 or 16B
    const uint32_t brow8 = (uint32_t)(lane & 7);
    const uint32_t bcolq = (uint32_t)(((lane >> 3) & 1) * 8) * 2;   // 0 or 16B

    float acc[4][8][4];
    #pragma unroll
    for (int mi = 0; mi < 4; mi++)
        #pragma unroll
        for (int ni = 0; ni < 8; ni++)
            #pragma unroll
            for (int j = 0; j < 4; j++) acc[mi][ni][j] = 0.f;

    auto issue = [&](int kt, int st) {
        const int k0 = kt * BK;
        const uint32_t sbase = sb + st * STAGE;
        // A: 1024 cp16 over 128 threads (8 each)
        #pragma unroll
        for (int i = 0; i < 8; i++) {
            int idx = i * THREADS + tid;
            int r = idx >> 3, u = idx & 7;
            cp16(sbase + A_OFF + r * ROWB + u * 16,
                 g_xh + (size_t)(row0 + r) * IN_DIM + k0 + u * 8);
        }
        // B: 1024 cp16 over 128 threads (8 each)
        #pragma unroll
        for (int i = 0; i < 8; i++) {
            int idx = i * THREADS + tid;
            int r = idx >> 3, u = idx & 7;
            cp16(sbase + B_OFF + r * ROWB + u * 16,
                 g_Wh + (size_t)(n0 + r) * IN_DIM + k0 + u * 8);
        }
        asm volatile("cp.async.commit_group;" ::: "memory");
    };

    // ---- prologue: 2 chunks in flight ---------------------------------------
    issue(0, 0);
    issue(1, 1);

    // ---- main loop ----------------------------------------------------------
    for (int kt = 0; kt < NCHUNK; kt++) {
        const int st = kt % NSTAGE;
        asm volatile("cp.async.wait_group 1;" ::: "memory");   // chunk kt ready
        __syncthreads();

        // early prefetch of chunk kt+2 (its stage was consumed at chunk kt-1)
        if (kt + 2 < NCHUNK) issue(kt + 2, (kt + 2) % NSTAGE);
        else asm volatile("cp.async.commit_group;" ::: "memory"); // keep count

        const uint32_t sbase = sb + st * STAGE;
        #pragma unroll
        for (int s = 0; s < 4; s++) {
            const uint32_t kb = (uint32_t)(s * 16) * 2;         // 32B per k16

            uint32_t af[4][4];
            #pragma unroll
            for (int mi = 0; mi < 4; mi++)
                ldx4(af[mi], sbase + A_OFF + (arow + mi * 16) * ROWB + kb + acolq);

            uint32_t bf[8][2];
            #pragma unroll
            for (int ni = 0; ni < 8; ni++)
                ldx2(bf[ni], sbase + B_OFF +
                     (warp_n * 64 + ni * 8 + brow8) * ROWB + kb + bcolq);

            #pragma unroll
            for (int mi = 0; mi < 4; mi++)
                #pragma unroll
                for (int ni = 0; ni < 8; ni++)
                    mma16816(acc[mi][ni], af[mi], bf[ni]);
        }
    }

    // ---- epilogue: bias + relu + float2 stores ------------------------------
    #pragma unroll
    for (int mi = 0; mi < 4; mi++) {
        int r = row0 + warp_m * 64 + mi * 16 + (lane >> 2);
        #pragma unroll
        for (int ni = 0; ni < 8; ni++) {
            int col = n0 + warp_n * 64 + ni * 8 + (lane & 3) * 2;
            float2 bv = *reinterpret_cast<const float2*>(bias + col);
            if (r < M) {
                float2 o;
                o.x = fmaxf(acc[mi][ni][0] + bv.x, 0.f);
                o.y = fmaxf(acc[mi][ni][1] + bv.y, 0.f);
                *reinterpret_cast<float2*>(C + (size_t)r * OUT_DIM + col) = o;
            }
            if (r + 8 < M) {
                float2 o;
                o.x = fmaxf(acc[mi][ni][2] + bv.x, 0.f);
                o.y = fmaxf(acc[mi][ni][3] + bv.y, 0.f);
                *reinterpret_cast<float2*>(C + (size_t)(r + 8) * OUT_DIM + col) = o;
            }
        }
    }
}

// ---------------- scatter-add on column 0 -------------------------------------
__global__ void scatter_add_col0_kernel(const float* __restrict__ x,
                                        const int* __restrict__ edge_index,
                                        float* __restrict__ out,
                                        int E) {
    int e = blockIdx.x * blockDim.x + threadIdx.x;
    if (e < E) {
        int c = edge_index[E + e];            // row 1 of [2,E] int32
        atomicAdd(&out[(size_t)c * OUT_DIM], x[(size_t)e * IN_DIM]);
    }
}

// ---------------- launch ------------------------------------------------------
extern "C" void kernel_launch(void* const* d_in, const int* in_sizes, int n_in,
                              void* d_out, int out_size) {
    const float* x   = (const float*)d_in[0];
    const int*   ei  = (const int*)d_in[1];
    const float* W   = (const float*)d_in[2];
    const float* b   = (const float*)d_in[3];
    float*       out = (float*)d_out;

    const int M = in_sizes[0] / IN_DIM;
    const int E = in_sizes[1] / 2;

    cudaFuncSetAttribute(gemm_mma_kernel, cudaFuncAttributeMaxDynamicSharedMemorySize, SM_TOTAL);

    const int n4 = M * IN_DIM / 4;
    conv_xw_kernel<<<(n4 + 255) / 256, 256>>>(x, W, n4);

    dim3 grid(OUT_DIM / BN, (M + BM - 1) / BM);   // 4 x 782
    gemm_mma_kernel<<<grid, THREADS, SM_TOTAL>>>(b, out, M);

    scatter_add_col0_kernel<<<(E + 255) / 256, 256>>>(x, ei, out, E);
}

// round 12
// speedup vs baseline: 1.2837x; 1.1752x over previous
#include <cuda_runtime.h>
#include <cuda_fp16.h>
#include <cstdint>

// ----------------------------------------------------------------------------
// GNNLayer: out = relu(x @ W^T + b); out[col[e],0] += x[e,0]
// fp16 mma.sync GEMM with FUSED x fp32->fp16 conversion:
//   A: cp.async fp32 -> smem(288B rows) -> LDS.64 + cvt to fragments
//   B: fp16 (prep) -> cp.async -> ldmatrix
// CTA 128x128, 4 warps (2x2) of 64x64, 2 stages, 2 CTAs/SM.
// ----------------------------------------------------------------------------

#define IN_DIM  512
#define OUT_DIM 512
#define BM      128
#define BN      128
#define BK      64
#define NCHUNK  (IN_DIM / BK)   // 8
#define THREADS 128

// A fp32 tile: 128 rows x 64 floats; row stride 288B (256 + 32 pad):
// 72 words == 8 mod 32 -> fragment LDS.64 pattern conflict-free.
#define A32_ROWB 288
// B fp16 tile: 128 rows x 64 halves; row stride 144B (ldmatrix conflict-free).
#define B_ROWB   144
#define SM_A     0
#define SM_B     (BM * A32_ROWB)             // 36864
#define STAGE    (SM_B + BM * B_ROWB)        // 55296
#define NSTAGE   2
#define SM_TOTAL (NSTAGE * STAGE)            // 110592 (x2 CTA = 221184 <= 228KB)

__device__ __half g_Wh[OUT_DIM * IN_DIM];

__device__ __forceinline__ uint32_t smem_u32(const void* p) {
    uint32_t a;
    asm("{ .reg .u64 t; cvta.to.shared.u64 t, %1; cvt.u32.u64 %0, t; }" : "=r"(a) : "l"(p));
    return a;
}
__device__ __forceinline__ void ldx2(uint32_t r[2], uint32_t addr) {
    asm volatile("ldmatrix.sync.aligned.m8n8.x2.shared.b16 {%0,%1}, [%2];"
                 : "=r"(r[0]), "=r"(r[1]) : "r"(addr));
}
__device__ __forceinline__ void mma16816(float c[4], const uint32_t a[4], const uint32_t b[2]) {
    asm volatile("mma.sync.aligned.m16n8k16.row.col.f32.f16.f16.f32 "
                 "{%0,%1,%2,%3}, {%4,%5,%6,%7}, {%8,%9}, {%0,%1,%2,%3};"
                 : "+f"(c[0]), "+f"(c[1]), "+f"(c[2]), "+f"(c[3])
                 : "r"(a[0]), "r"(a[1]), "r"(a[2]), "r"(a[3]), "r"(b[0]), "r"(b[1]));
}
__device__ __forceinline__ void cp16(uint32_t dst, const void* src) {
    asm volatile("cp.async.cg.shared.global [%0], [%1], 16;"
                 :: "r"(dst), "l"(__cvta_generic_to_global(src)));
}
// LDS.64 of two fp32 from shared, convert to packed fp16x2 (low = first)
__device__ __forceinline__ uint32_t lds2cvt(uint32_t addr) {
    float f0, f1;
    asm volatile("ld.shared.v2.f32 {%0, %1}, [%2];" : "=f"(f0), "=f"(f1) : "r"(addr));
    __half2 h = __floats2half2_rn(f0, f1);
    return *reinterpret_cast<uint32_t*>(&h);
}

// ---------------- prep: convert W to fp16 (1MB, ~4.5us) -----------------------
__global__ void conv_W_kernel(const float* __restrict__ W) {
    int i = blockIdx.x * blockDim.x + threadIdx.x;
    if (i < OUT_DIM * IN_DIM) g_Wh[i] = __float2half_rn(W[i]);
}

// ---------------- main GEMM kernel --------------------------------------------
__global__ __launch_bounds__(THREADS, 2)
void gemm_mma_kernel(const float* __restrict__ A,      // fp32 x
                     const float* __restrict__ bias,
                     float* __restrict__ C, int M) {
    extern __shared__ char smem[];
    const uint32_t sb = smem_u32(smem);
    const int tid    = threadIdx.x;
    const int lane   = tid & 31;
    const int wid    = tid >> 5;          // 0..3
    const int warp_m = wid >> 1;          // 0..1 (64 rows)
    const int warp_n = wid & 1;           // 0..1 (64 cols)
    const int row0   = blockIdx.y * BM;
    const int n0     = blockIdx.x * BN;

    // A fragment addressing (fp32 in smem): lane covers rows +lane/4, k-offsets 2*(lane%4)
    const uint32_t a_r  = (uint32_t)(warp_m * 64 + (lane >> 2));
    const uint32_t a_c  = (uint32_t)(2 * (lane & 3));              // float offset
    // B ldmatrix addressing (fp16): R11-proven
    const uint32_t brow8 = (uint32_t)(lane & 7);
    const uint32_t bcolq = (uint32_t)(((lane >> 3) & 1) * 8) * 2;  // 0 or 16B

    float acc[4][8][4];
    #pragma unroll
    for (int mi = 0; mi < 4; mi++)
        #pragma unroll
        for (int ni = 0; ni < 8; ni++)
            #pragma unroll
            for (int j = 0; j < 4; j++) acc[mi][ni][j] = 0.f;

    auto issue = [&](int kt, int st) {
        const int k0 = kt * BK;
        const uint32_t sbase = sb + st * STAGE;
        // A: fp32, 128 rows x 16 units of 16B = 2048 cp16 (16/thread), guarded
        #pragma unroll
        for (int i = 0; i < 16; i++) {
            int idx = i * THREADS + tid;
            int r = idx >> 4, u = idx & 15;
            int gr = row0 + r;
            if (gr < M)
                cp16(sbase + SM_A + r * A32_ROWB + u * 16,
                     A + (size_t)gr * IN_DIM + k0 + u * 4);
        }
        // B: fp16, 128 rows x 8 units = 1024 cp16 (8/thread)
        #pragma unroll
        for (int i = 0; i < 8; i++) {
            int idx = i * THREADS + tid;
            int r = idx >> 3, u = idx & 7;
            cp16(sbase + SM_B + r * B_ROWB + u * 16,
                 g_Wh + (size_t)(n0 + r) * IN_DIM + k0 + u * 8);
        }
        asm volatile("cp.async.commit_group;" ::: "memory");
    };

    // ---- prologue: both stages in flight ------------------------------------
    issue(0, 0);
    issue(1, 1);

    // ---- main loop ----------------------------------------------------------
    for (int kt = 0; kt < NCHUNK; kt++) {
        const int st = kt & 1;
        asm volatile("cp.async.wait_group 1;" ::: "memory");   // chunk kt landed
        __syncthreads();

        const uint32_t sbase = sb + st * STAGE;
        #pragma unroll
        for (int s = 0; s < 4; s++) {
            // ---- A fragments: LDS.64 fp32 pairs -> cvt to fp16x2 ------------
            uint32_t af[4][4];
            #pragma unroll
            for (int mi = 0; mi < 4; mi++) {
                uint32_t base = sbase + SM_A + (a_r + mi * 16) * A32_ROWB
                              + (s * 16 + a_c) * 4;
                af[mi][0] = lds2cvt(base);                       // (r,   k..k+1)
                af[mi][1] = lds2cvt(base + 8 * A32_ROWB);        // (r+8, k..k+1)
                af[mi][2] = lds2cvt(base + 32);                  // (r,   k+8..9)
                af[mi][3] = lds2cvt(base + 8 * A32_ROWB + 32);   // (r+8, k+8..9)
            }
            // ---- B fragments: ldmatrix fp16 ---------------------------------
            const uint32_t kb = (uint32_t)(s * 16) * 2;          // 32B per k16
            uint32_t bf[8][2];
            #pragma unroll
            for (int ni = 0; ni < 8; ni++)
                ldx2(bf[ni], sbase + SM_B +
                     (warp_n * 64 + ni * 8 + brow8) * B_ROWB + kb + bcolq);

            #pragma unroll
            for (int mi = 0; mi < 4; mi++)
                #pragma unroll
                for (int ni = 0; ni < 8; ni++)
                    mma16816(acc[mi][ni], af[mi], bf[ni]);
        }

        __syncthreads();                                        // stage consumed
        if (kt + 2 < NCHUNK) issue(kt + 2, st);
        else asm volatile("cp.async.commit_group;" ::: "memory"); // keep count
    }

    // ---- epilogue: bias + relu + float2 stores ------------------------------
    #pragma unroll
    for (int mi = 0; mi < 4; mi++) {
        int r = row0 + warp_m * 64 + mi * 16 + (lane >> 2);
        #pragma unroll
        for (int ni = 0; ni < 8; ni++) {
            int col = n0 + warp_n * 64 + ni * 8 + (lane & 3) * 2;
            float2 bv = *reinterpret_cast<const float2*>(bias + col);
            if (r < M) {
                float2 o;
                o.x = fmaxf(acc[mi][ni][0] + bv.x, 0.f);
                o.y = fmaxf(acc[mi][ni][1] + bv.y, 0.f);
                *reinterpret_cast<float2*>(C + (size_t)r * OUT_DIM + col) = o;
            }
            if (r + 8 < M) {
                float2 o;
                o.x = fmaxf(acc[mi][ni][2] + bv.x, 0.f);
                o.y = fmaxf(acc[mi][ni][3] + bv.y, 0.f);
                *reinterpret_cast<float2*>(C + (size_t)(r + 8) * OUT_DIM + col) = o;
            }
        }
    }
}

// ---------------- scatter-add on column 0 -------------------------------------
__global__ void scatter_add_col0_kernel(const float* __restrict__ x,
                                        const int* __restrict__ edge_index,
                                        float* __restrict__ out,
                                        int E) {
    int e = blockIdx.x * blockDim.x + threadIdx.x;
    if (e < E) {
        int c = edge_index[E + e];            // row 1 of [2,E] int32
        atomicAdd(&out[(size_t)c * OUT_DIM], x[(size_t)e * IN_DIM]);
    }
}

// ---------------- launch ------------------------------------------------------
extern "C" void kernel_launch(void* const* d_in, const int* in_sizes, int n_in,
                              void* d_out, int out_size) {
    const float* x   = (const float*)d_in[0];
    const int*   ei  = (const int*)d_in[1];
    const float* W   = (const float*)d_in[2];
    const float* b   = (const float*)d_in[3];
    float*       out = (float*)d_out;

    const int M = in_sizes[0] / IN_DIM;
    const int E = in_sizes[1] / 2;

    cudaFuncSetAttribute(gemm_mma_kernel, cudaFuncAttributeMaxDynamicSharedMemorySize, SM_TOTAL);

    conv_W_kernel<<<(OUT_DIM * IN_DIM + 255) / 256, 256>>>(W);

    dim3 grid(OUT_DIM / BN, (M + BM - 1) / BM);   // 4 x 782
    gemm_mma_kernel<<<grid, THREADS, SM_TOTAL>>>(x, b, out, M);

    scatter_add_col0_kernel<<<(E + 255) / 256, 256>>>(x, ei, out, E);
}